// round 9
// baseline (speedup 1.0000x reference)
#include <cuda_runtime.h>
#include <math.h>

#define N0 2048
#define D0 3
#define N1 1024
#define D1 5
#define TS 32
#define T0 64
#define T1 32
#define NBLK0 2080
#define NBLK1 528
#define NBLK  2608
#define PAIR_THREADS 256
#define GRID_PAIR 592               // 148 * 4

// global/smem record sizes (floats)
#define A0_REC 24   // pair record: 3 r x 4 k(pad) x 2 halves
#define B0_ROW 20   // j row: 9 dup'd ull + 1 pad ull
#define A1_REC 60   // pair record: 5 r x 6 k(pad) x 2 halves
#define B1_ROW 60   // j row: 5 c x 6 k(pad) x 2 (TRANSPOSED, dup'd)
#define NA0_F4 96   // 16*A0_REC/4
#define NB0_F4 160  // 32*B0_ROW/4
#define NA1_F4 240
#define NB1_F4 480

typedef unsigned long long ull;

// Scratch (device globals: allocation-free per harness rules)
__device__ __align__(16) float g_A0[(N0 / 2) * A0_REC];
__device__ __align__(16) float g_B0[N0 * B0_ROW];
__device__ __align__(16) float g_A1[(N1 / 2) * A1_REC];
__device__ __align__(16) float g_B1[N1 * B1_ROW];
__device__ unsigned g_tile[NBLK];
__device__ double g_sum0;
__device__ double g_sum1;
__device__ unsigned int g_done = 0;

// ---------------- packed f32x2 helpers (FFMA2: PTX-only) ----------------
__device__ __forceinline__ ull f2dup(float v) {
    ull r;
    asm("mov.b64 %0, {%1, %1};" : "=l"(r) : "f"(v));
    return r;
}
__device__ __forceinline__ void f2unpack(ull v, float& lo, float& hi) {
    asm("mov.b64 {%0, %1}, %2;" : "=f"(lo), "=f"(hi) : "l"(v));
}
__device__ __forceinline__ ull fma2(ull a, ull b, ull c) {
    ull d;
    asm("fma.rn.f32x2 %0, %1, %2, %3;" : "=l"(d) : "l"(a), "l"(b), "l"(c));
    return d;
}
__device__ __forceinline__ ull add2(ull a, ull b) {
    ull d;
    asm("add.rn.f32x2 %0, %1, %2;" : "=l"(d) : "l"(a), "l"(b));
    return d;
}

__device__ __forceinline__ void tri_decode(int b, int& ti, int& tj) {
    ti = (int)((sqrtf(8.f * (float)b + 1.f) - 1.f) * 0.5f);
    while ((ti + 1) * (ti + 2) / 2 <= b) ti++;
    while (ti * (ti + 1) / 2 > b) ti--;
    tj = b - ti * (ti + 1) / 2;
}

// ---------------- Fused prep: normalize+invert, emit packed layouts + decode table ----------------
__global__ void __launch_bounds__(32) prep_kernel(const float* __restrict__ k0,
                                                  const float* __restrict__ k1) {
    int gid = blockIdx.x * 32 + threadIdx.x;
    if (gid == 0) {
        g_sum0 = 0.0;
        g_sum1 = 0.0;
    }
    // decode table (one entry per thread; D=5 jobs occupy [0, NBLK1))
    if (gid < NBLK) {
        int ti, tj;
        if (gid < NBLK1) tri_decode(gid, ti, tj);
        else             tri_decode(gid - NBLK1, ti, tj);
        g_tile[gid] = ((unsigned)ti << 8) | (unsigned)tj;
    }

    if (blockIdx.x < 64) {
        int i = gid;  // layer0 matrix
        float a[9];
        float ss = 0.f;
#pragma unroll
        for (int t = 0; t < 9; t++) {
            a[t] = k0[i * 9 + t];
            ss = fmaf(a[t], a[t], ss);
        }
        float rn = 1.f / (sqrtf(ss) + 1e-8f);
#pragma unroll
        for (int t = 0; t < 9; t++) {
            a[t] *= rn;
            g_B0[i * B0_ROW + 2 * t + 0] = a[t];  // duplicated
            g_B0[i * B0_ROW + 2 * t + 1] = a[t];
        }
        g_B0[i * B0_ROW + 18] = 0.f;
        g_B0[i * B0_ROW + 19] = 0.f;

        float inv[9];
        float c00 = a[4] * a[8] - a[5] * a[7];
        float c10 = a[5] * a[6] - a[3] * a[8];
        float c20 = a[3] * a[7] - a[4] * a[6];
        float det = a[0] * c00 + a[1] * c10 + a[2] * c20;
        float id = -1.f / det;  // negated inverse
        inv[0] = c00 * id;
        inv[1] = (a[2] * a[7] - a[1] * a[8]) * id;
        inv[2] = (a[1] * a[5] - a[2] * a[4]) * id;
        inv[3] = c10 * id;
        inv[4] = (a[0] * a[8] - a[2] * a[6]) * id;
        inv[5] = (a[2] * a[3] - a[0] * a[5]) * id;
        inv[6] = c20 * id;
        inv[7] = (a[1] * a[6] - a[0] * a[7]) * id;
        inv[8] = (a[0] * a[4] - a[1] * a[3]) * id;
        int pair = i >> 1, h = i & 1;
        float* rec = &g_A0[pair * A0_REC];
#pragma unroll
        for (int r = 0; r < 3; r++) {
#pragma unroll
            for (int k = 0; k < 3; k++)
                rec[(r * 4 + k) * 2 + h] = inv[r * 3 + k];
            rec[(r * 4 + 3) * 2 + h] = 0.f;
        }
    } else {
        int i = gid - 2048;  // layer1 matrix
        float a[5][5], b[5][5];
        float ss = 0.f;
#pragma unroll
        for (int r = 0; r < 5; r++)
#pragma unroll
            for (int c = 0; c < 5; c++) {
                float v = k1[i * 25 + r * 5 + c];
                a[r][c] = v;
                ss = fmaf(v, v, ss);
            }
        float rn = 1.f / (sqrtf(ss) + 1e-8f);
#pragma unroll
        for (int r = 0; r < 5; r++)
#pragma unroll
            for (int c = 0; c < 5; c++) {
                a[r][c] *= rn;
                b[r][c] = (r == c) ? 1.f : 0.f;
            }
        // B transposed + duplicated: row j holds cols [c][k] = kn[k*5+c]
        float* brow = &g_B1[i * B1_ROW];
#pragma unroll
        for (int c = 0; c < 5; c++) {
#pragma unroll
            for (int k = 0; k < 5; k++) {
                float v = a[k][c];
                brow[(c * 6 + k) * 2 + 0] = v;
                brow[(c * 6 + k) * 2 + 1] = v;
            }
            brow[(c * 6 + 5) * 2 + 0] = 0.f;
            brow[(c * 6 + 5) * 2 + 1] = 0.f;
        }
        // Gauss-Jordan, static indices, predicated pivot swaps
#pragma unroll
        for (int col = 0; col < 5; col++) {
#pragma unroll
            for (int r = col + 1; r < 5; r++) {
                bool sw = fabsf(a[r][col]) > fabsf(a[col][col]);
#pragma unroll
                for (int c = 0; c < 5; c++) {
                    float t0 = a[col][c], t1 = a[r][c];
                    a[col][c] = sw ? t1 : t0;
                    a[r][c]   = sw ? t0 : t1;
                    float u0 = b[col][c], u1 = b[r][c];
                    b[col][c] = sw ? u1 : u0;
                    b[r][c]   = sw ? u0 : u1;
                }
            }
            float piv = 1.f / a[col][col];
#pragma unroll
            for (int c = 0; c < 5; c++) {
                a[col][c] *= piv;
                b[col][c] *= piv;
            }
#pragma unroll
            for (int r = 0; r < 5; r++) {
                if (r == col) continue;
                float f = a[r][col];
#pragma unroll
                for (int c = 0; c < 5; c++) {
                    a[r][c] = fmaf(-f, a[col][c], a[r][c]);
                    b[r][c] = fmaf(-f, b[col][c], b[r][c]);
                }
            }
        }
        int pair = i >> 1, h = i & 1;
        float* rec = &g_A1[pair * A1_REC];
#pragma unroll
        for (int r = 0; r < 5; r++) {
#pragma unroll
            for (int k = 0; k < 5; k++)
                rec[(r * 6 + k) * 2 + h] = -b[r][k];  // negated
            rec[(r * 6 + 5) * 2 + h] = 0.f;
        }
    }
}

// ---------------- prefetch (pure f4 memcpy, layout == smem) ----------------
__device__ __forceinline__ void prefetch(int job, int t, float4* pf) {
    if (job >= NBLK) return;
    unsigned tt = g_tile[job];
    int ti = tt >> 8, tj = tt & 255;
    if (job < NBLK1) {
        const float4* As = (const float4*)(g_A1 + ti * 16 * A1_REC);
        const float4* Bs = (const float4*)(g_B1 + tj * TS * B1_ROW);
#pragma unroll
        for (int k = 0; k < 3; k++) {
            int idx = t + k * PAIR_THREADS;
            if (idx < NA1_F4) pf[k] = As[idx];
            else if (idx < NA1_F4 + NB1_F4) pf[k] = Bs[idx - NA1_F4];
        }
    } else {
        const float4* As = (const float4*)(g_A0 + ti * 16 * A0_REC);
        const float4* Bs = (const float4*)(g_B0 + tj * TS * B0_ROW);
        if (t < NA0_F4) pf[0] = As[t];
        else pf[0] = Bs[t - NA0_F4];
    }
}

__device__ __forceinline__ void stage(bool d5, int t, const float4* pf,
                                      float4* sA4, float4* sB4) {
    if (d5) {
#pragma unroll
        for (int k = 0; k < 3; k++) {
            int idx = t + k * PAIR_THREADS;
            if (idx < NA1_F4) sA4[idx] = pf[k];
            else if (idx < NA1_F4 + NB1_F4) sB4[idx - NA1_F4] = pf[k];
        }
    } else {
        if (t < NA0_F4) sA4[t] = pf[0];
        else sB4[t - NA0_F4] = pf[0];
    }
}

// ---------------- compute: D=3 tile (B resident, r-outer) ----------------
__device__ __forceinline__ void compute3(unsigned tt, const float* sA, const float* sB,
                                         int t, float& val) {
    const int ti = tt >> 8, tj = tt & 255;
    const int w = t >> 5, l = t & 31;
    const int j = tj * TS + l;
    const bool diag = (ti == tj);
    const ull* Bp = (const ull*)(sB + l * B0_ROW);
    ulonglong2 b01 = *(const ulonglong2*)(Bp + 0);
    ulonglong2 b23 = *(const ulonglong2*)(Bp + 2);
    ulonglong2 b45 = *(const ulonglong2*)(Bp + 4);
    ulonglong2 b67 = *(const ulonglong2*)(Bp + 6);
    ull b8 = Bp[8];
    ull B2[9] = {b01.x, b01.y, b23.x, b23.y, b45.x, b45.y, b67.x, b67.y, b8};
    const ull eye2 = f2dup(1.f);
#pragma unroll
    for (int p = 0; p < 2; p++) {
        const int pair = 2 * w + p;
        const int i0 = ti * TS + 2 * pair;
        const ull* Ap = (const ull*)(sA + pair * A0_REC);
        ull s2a = 0, s2b = 0;
#pragma unroll
        for (int r = 0; r < 3; r++) {
            ulonglong2 a01 = *(const ulonglong2*)(Ap + r * 4);
            ull a2 = Ap[r * 4 + 2];
#pragma unroll
            for (int c = 0; c < 3; c++) {
                ull acc = fma2(a01.x, B2[c], 0ULL);
                acc = fma2(a01.y, B2[3 + c], acc);
                acc = fma2(a2, B2[6 + c], acc);
                if (r == c) acc = add2(acc, eye2);
                if (c & 1) s2b = fma2(acc, acc, s2b);
                else       s2a = fma2(acc, acc, s2a);
            }
        }
        ull s2 = add2(s2a, s2b);
        float lo, hi;
        f2unpack(s2, lo, hi);
        if ((!diag || i0 > j) && lo < 1.f) val += 1.f - sqrtf(lo);
        if ((!diag || i0 + 1 > j) && hi < 1.f) val += 1.f - sqrtf(hi);
    }
}

// ---------------- compute: D=5 tile (c-outer, transposed dup'd B) ----------------
__device__ __forceinline__ void compute5(unsigned tt, const float* sA, const float* sB,
                                         int t, float& val) {
    const int ti = tt >> 8, tj = tt & 255;
    const int w = t >> 5, l = t & 31;
    const int j = tj * TS + l;
    const bool diag = (ti == tj);
    const float* Bb = sB + l * B1_ROW;
    const ull* Ap0 = (const ull*)(sA + (2 * w) * A1_REC);
    const ull* Ap1 = (const ull*)(sA + (2 * w + 1) * A1_REC);
    const ull eye2 = f2dup(1.f);
    ull s2[4] = {0, 0, 0, 0};  // [pair][chain]
#pragma unroll
    for (int c = 0; c < 5; c++) {
        const ull* bp = (const ull*)(Bb + c * 12);
        ulonglong2 v0 = *(const ulonglong2*)(bp + 0);
        ulonglong2 v1 = *(const ulonglong2*)(bp + 2);
        ull bt0 = v0.x, bt1 = v0.y, bt2 = v1.x, bt3 = v1.y, bt4 = bp[4];
#pragma unroll
        for (int r = 0; r < 5; r++) {
#pragma unroll
            for (int p = 0; p < 2; p++) {
                const ull* Ar = (p ? Ap1 : Ap0) + r * 6;
                ulonglong2 a01 = *(const ulonglong2*)(Ar + 0);
                ulonglong2 a23 = *(const ulonglong2*)(Ar + 2);
                ull a4 = Ar[4];
                ull acc = fma2(a01.x, bt0, 0ULL);
                acc = fma2(a01.y, bt1, acc);
                acc = fma2(a23.x, bt2, acc);
                acc = fma2(a23.y, bt3, acc);
                acc = fma2(a4, bt4, acc);
                if (r == c) acc = add2(acc, eye2);
                const int ch = p * 2 + (r & 1);
                s2[ch] = fma2(acc, acc, s2[ch]);
            }
        }
    }
#pragma unroll
    for (int p = 0; p < 2; p++) {
        ull s = add2(s2[p * 2], s2[p * 2 + 1]);
        float lo, hi;
        f2unpack(s, lo, hi);
        const int i0 = ti * TS + w * 4 + 2 * p;
        if ((!diag || i0 > j) && lo < 1.f) val += 1.f - sqrtf(lo);
        if ((!diag || i0 + 1 > j) && hi < 1.f) val += 1.f - sqrtf(hi);
    }
}

// ---------------- Persistent, pipelined pair kernel ----------------
__global__ void __launch_bounds__(PAIR_THREADS, 4) pair_all_kernel(float* __restrict__ out) {
    __shared__ __align__(16) float sA[2][16 * A1_REC];   // 960 fl / buf
    __shared__ __align__(16) float sB[2][TS * B1_ROW];   // 1920 fl / buf
    __shared__ float warp_sums[2][PAIR_THREADS / 32];

    const int t = threadIdx.x;
    float val0 = 0.f, val1 = 0.f;

    float4 pf[3];
    int job = blockIdx.x;
    prefetch(job, t, pf);
    int buf = 0;
    while (job < NBLK) {
        const bool d5 = (job < NBLK1);
        stage(d5, t, pf, (float4*)sA[buf], (float4*)sB[buf]);
        __syncthreads();  // single barrier per tile (double buffer)
        const unsigned tt = g_tile[job];
        prefetch(job + GRID_PAIR, t, pf);  // hidden under compute
        if (d5) compute5(tt, sA[buf], sB[buf], t, val1);
        else    compute3(tt, sA[buf], sB[buf], t, val0);
        buf ^= 1;
        job += GRID_PAIR;
    }

    // block reduction of both accumulators
#pragma unroll
    for (int off = 16; off > 0; off >>= 1) {
        val0 += __shfl_down_sync(0xFFFFFFFFu, val0, off);
        val1 += __shfl_down_sync(0xFFFFFFFFu, val1, off);
    }
    if ((t & 31) == 0) {
        warp_sums[0][t >> 5] = val0;
        warp_sums[1][t >> 5] = val1;
    }
    __syncthreads();
    if (t == 0) {
        float b0 = 0.f, b1 = 0.f;
#pragma unroll
        for (int ww = 0; ww < PAIR_THREADS / 32; ww++) {
            b0 += warp_sums[0][ww];
            b1 += warp_sums[1][ww];
        }
        if (b0 != 0.f) atomicAdd(&g_sum0, (double)b0);
        if (b1 != 0.f) atomicAdd(&g_sum1, (double)b1);
        __threadfence();
        unsigned int done = atomicAdd(&g_done, 1u);
        if (done == GRID_PAIR - 1) {
            __threadfence();
            double s0 = *(volatile double*)&g_sum0;
            double s1 = *(volatile double*)&g_sum1;
            double l0 = 2.0 * s0 / ((double)N0 * (double)(N0 - 1));
            double l1 = 2.0 * s1 / ((double)N1 * (double)(N1 - 1));
            out[0] = (float)(0.5 * (l0 + l1));
            g_done = 0;  // reset for next graph replay
        }
    }
}

extern "C" void kernel_launch(void* const* d_in, const int* in_sizes, int n_in,
                              void* d_out, int out_size) {
    const float* k0 = (const float*)d_in[0];
    const float* k1 = (const float*)d_in[1];
    float* out = (float*)d_out;

    prep_kernel<<<96, 32>>>(k0, k1);
    pair_all_kernel<<<GRID_PAIR, PAIR_THREADS>>>(out);
}

// round 10
// speedup vs baseline: 1.2177x; 1.2177x over previous
#include <cuda_runtime.h>
#include <math.h>

#define N0 2048
#define D0 3
#define N1 1024
#define D1 5
#define TS 32
#define NBLK0 2080
#define NBLK1 528
#define NBLK  2608
#define PAIR_THREADS 256
#define GRID_PAIR 592               // 148 * 4

// dot-product lengths (padded to /4)
#define L0 16      // 9 + 6 + 1 pad
#define L1 40      // 25 + 15
#define P0_REC 32  // L0 * 2 halves (i-pair record)
#define P1_REC 80  // L1 * 2
#define Q0_STR 36  // L0*2 dup + 4 pad  (odd 16B-granule stride: 36/4=9)
#define Q1_STR 84  // L1*2 dup + 4 pad  (84/4=21 odd)
#define NA0_F4 128  // 16*P0_REC/4
#define NB0_F4 288  // 32*Q0_STR/4
#define NA1_F4 320
#define NB1_F4 672

typedef unsigned long long ull;

// Scratch (device globals: allocation-free per harness rules)
__device__ __align__(16) float gP0[(N0 / 2) * P0_REC];
__device__ __align__(16) float gQ0[N0 * Q0_STR];
__device__ __align__(16) float gP1[(N1 / 2) * P1_REC];
__device__ __align__(16) float gQ1[N1 * Q1_STR];
__device__ unsigned g_tile[NBLK];
__device__ double g_sum0;
__device__ double g_sum1;
__device__ unsigned int g_done = 0;

// ---------------- packed f32x2 helpers (FFMA2: PTX-only) ----------------
__device__ __forceinline__ ull f2dup(float v) {
    ull r;
    asm("mov.b64 %0, {%1, %1};" : "=l"(r) : "f"(v));
    return r;
}
__device__ __forceinline__ void f2unpack(ull v, float& lo, float& hi) {
    asm("mov.b64 {%0, %1}, %2;" : "=f"(lo), "=f"(hi) : "l"(v));
}
__device__ __forceinline__ ull fma2(ull a, ull b, ull c) {
    ull d;
    asm("fma.rn.f32x2 %0, %1, %2, %3;" : "=l"(d) : "l"(a), "l"(b), "l"(c));
    return d;
}
__device__ __forceinline__ ull add2(ull a, ull b) {
    ull d;
    asm("add.rn.f32x2 %0, %1, %2;" : "=l"(d) : "l"(a), "l"(b));
    return d;
}

__device__ __forceinline__ void tri_decode(int b, int& ti, int& tj) {
    ti = (int)((sqrtf(8.f * (float)b + 1.f) - 1.f) * 0.5f);
    while ((ti + 1) * (ti + 2) / 2 <= b) ti++;
    while (ti * (ti + 1) / 2 > b) ti--;
    tj = b - ti * (ti + 1) / 2;
}

// ---------------- Fused prep: normalize+invert, emit dot-product features ----------------
// s_ij = D - 2 tr(inv_i kn_j) + <inv_i^T inv_i, kn_j kn_j^T> = D + p_i . q_j
__global__ void __launch_bounds__(32) prep_kernel(const float* __restrict__ k0,
                                                  const float* __restrict__ k1) {
    int gid = blockIdx.x * 32 + threadIdx.x;
    if (gid == 0) {
        g_sum0 = 0.0;
        g_sum1 = 0.0;
    }
    if (gid < NBLK) {
        int ti, tj;
        if (gid < NBLK1) tri_decode(gid, ti, tj);
        else             tri_decode(gid - NBLK1, ti, tj);
        g_tile[gid] = ((unsigned)ti << 8) | (unsigned)tj;
    }

    if (blockIdx.x < 64) {
        int i = gid;  // layer0 matrix
        float a[9];
        float ss = 0.f;
#pragma unroll
        for (int t = 0; t < 9; t++) {
            a[t] = k0[i * 9 + t];
            ss = fmaf(a[t], a[t], ss);
        }
        float rn = 1.f / (sqrtf(ss) + 1e-8f);
#pragma unroll
        for (int t = 0; t < 9; t++) a[t] *= rn;

        // q vector: z[0:9] = kn^T, z[9:12] = diag(H), z[12:15] = 2*offdiag(H), z[15]=0
        float z[L0];
#pragma unroll
        for (int r = 0; r < 3; r++)
#pragma unroll
            for (int k = 0; k < 3; k++)
                z[r * 3 + k] = a[k * 3 + r];
#pragma unroll
        for (int x = 0; x < 3; x++) {
            float h = 0.f;
#pragma unroll
            for (int c = 0; c < 3; c++) h = fmaf(a[x * 3 + c], a[x * 3 + c], h);
            z[9 + x] = h;
        }
        {
            int m = 0;
#pragma unroll
            for (int x = 0; x < 3; x++)
#pragma unroll
                for (int y = x + 1; y < 3; y++) {
                    float h = 0.f;
#pragma unroll
                    for (int c = 0; c < 3; c++) h = fmaf(a[x * 3 + c], a[y * 3 + c], h);
                    z[12 + m] = 2.f * h;
                    m++;
                }
        }
        z[15] = 0.f;
        float* qrow = &gQ0[i * Q0_STR];
#pragma unroll
        for (int q = 0; q < L0; q++) {
            qrow[2 * q + 0] = z[q];
            qrow[2 * q + 1] = z[q];
        }
#pragma unroll
        for (int q = 2 * L0; q < Q0_STR; q++) qrow[q] = 0.f;

        // inverse (adjugate)
        float inv[9];
        float c00 = a[4] * a[8] - a[5] * a[7];
        float c10 = a[5] * a[6] - a[3] * a[8];
        float c20 = a[3] * a[7] - a[4] * a[6];
        float det = a[0] * c00 + a[1] * c10 + a[2] * c20;
        float id = 1.f / det;
        inv[0] = c00 * id;
        inv[1] = (a[2] * a[7] - a[1] * a[8]) * id;
        inv[2] = (a[1] * a[5] - a[2] * a[4]) * id;
        inv[3] = c10 * id;
        inv[4] = (a[0] * a[8] - a[2] * a[6]) * id;
        inv[5] = (a[2] * a[3] - a[0] * a[5]) * id;
        inv[6] = c20 * id;
        inv[7] = (a[1] * a[6] - a[0] * a[7]) * id;
        inv[8] = (a[0] * a[4] - a[1] * a[3]) * id;

        // p vector: p[0:9] = -2*inv, p[9:12] = diag(G), p[12:15] = offdiag(G), p[15]=0
        float p[L0];
#pragma unroll
        for (int t = 0; t < 9; t++) p[t] = -2.f * inv[t];
#pragma unroll
        for (int x = 0; x < 3; x++) {
            float g = 0.f;
#pragma unroll
            for (int r = 0; r < 3; r++) g = fmaf(inv[r * 3 + x], inv[r * 3 + x], g);
            p[9 + x] = g;
        }
        {
            int m = 0;
#pragma unroll
            for (int x = 0; x < 3; x++)
#pragma unroll
                for (int y = x + 1; y < 3; y++) {
                    float g = 0.f;
#pragma unroll
                    for (int r = 0; r < 3; r++) g = fmaf(inv[r * 3 + x], inv[r * 3 + y], g);
                    p[12 + m] = g;
                    m++;
                }
        }
        p[15] = 0.f;
        int pair = i >> 1, h = i & 1;
        float* rec = &gP0[pair * P0_REC];
#pragma unroll
        for (int q = 0; q < L0; q++) rec[2 * q + h] = p[q];
    } else {
        int i = gid - 2048;  // layer1 matrix
        float a[5][5], b[5][5];
        float ss = 0.f;
#pragma unroll
        for (int r = 0; r < 5; r++)
#pragma unroll
            for (int c = 0; c < 5; c++) {
                float v = k1[i * 25 + r * 5 + c];
                a[r][c] = v;
                ss = fmaf(v, v, ss);
            }
        float rn = 1.f / (sqrtf(ss) + 1e-8f);
#pragma unroll
        for (int r = 0; r < 5; r++)
#pragma unroll
            for (int c = 0; c < 5; c++) {
                a[r][c] *= rn;
                b[r][c] = (r == c) ? 1.f : 0.f;
            }

        // q vector: z[0:25] = kn^T, z[25:30] = diag(H), z[30:40] = 2*offdiag(H)
        float z[L1];
#pragma unroll
        for (int r = 0; r < 5; r++)
#pragma unroll
            for (int k = 0; k < 5; k++)
                z[r * 5 + k] = a[k][r];
#pragma unroll
        for (int x = 0; x < 5; x++) {
            float h = 0.f;
#pragma unroll
            for (int c = 0; c < 5; c++) h = fmaf(a[x][c], a[x][c], h);
            z[25 + x] = h;
        }
        {
            int m = 0;
#pragma unroll
            for (int x = 0; x < 5; x++)
#pragma unroll
                for (int y = x + 1; y < 5; y++) {
                    float h = 0.f;
#pragma unroll
                    for (int c = 0; c < 5; c++) h = fmaf(a[x][c], a[y][c], h);
                    z[30 + m] = 2.f * h;
                    m++;
                }
        }
        float* qrow = &gQ1[i * Q1_STR];
#pragma unroll
        for (int q = 0; q < L1; q++) {
            qrow[2 * q + 0] = z[q];
            qrow[2 * q + 1] = z[q];
        }
#pragma unroll
        for (int q = 2 * L1; q < Q1_STR; q++) qrow[q] = 0.f;

        // Gauss-Jordan inverse, static indices, predicated pivot swaps
#pragma unroll
        for (int col = 0; col < 5; col++) {
#pragma unroll
            for (int r = col + 1; r < 5; r++) {
                bool sw = fabsf(a[r][col]) > fabsf(a[col][col]);
#pragma unroll
                for (int c = 0; c < 5; c++) {
                    float t0 = a[col][c], t1 = a[r][c];
                    a[col][c] = sw ? t1 : t0;
                    a[r][c]   = sw ? t0 : t1;
                    float u0 = b[col][c], u1 = b[r][c];
                    b[col][c] = sw ? u1 : u0;
                    b[r][c]   = sw ? u0 : u1;
                }
            }
            float piv = 1.f / a[col][col];
#pragma unroll
            for (int c = 0; c < 5; c++) {
                a[col][c] *= piv;
                b[col][c] *= piv;
            }
#pragma unroll
            for (int r = 0; r < 5; r++) {
                if (r == col) continue;
                float f = a[r][col];
#pragma unroll
                for (int c = 0; c < 5; c++) {
                    a[r][c] = fmaf(-f, a[col][c], a[r][c]);
                    b[r][c] = fmaf(-f, b[col][c], b[r][c]);
                }
            }
        }

        // p vector: p[0:25] = -2*inv, p[25:30] = diag(G), p[30:40] = offdiag(G)
        float p[L1];
#pragma unroll
        for (int r = 0; r < 5; r++)
#pragma unroll
            for (int k = 0; k < 5; k++)
                p[r * 5 + k] = -2.f * b[r][k];
#pragma unroll
        for (int x = 0; x < 5; x++) {
            float g = 0.f;
#pragma unroll
            for (int r = 0; r < 5; r++) g = fmaf(b[r][x], b[r][x], g);
            p[25 + x] = g;
        }
        {
            int m = 0;
#pragma unroll
            for (int x = 0; x < 5; x++)
#pragma unroll
                for (int y = x + 1; y < 5; y++) {
                    float g = 0.f;
#pragma unroll
                    for (int r = 0; r < 5; r++) g = fmaf(b[r][x], b[r][y], g);
                    p[30 + m] = g;
                    m++;
                }
        }
        int pair = i >> 1, h = i & 1;
        float* rec = &gP1[pair * P1_REC];
#pragma unroll
        for (int q = 0; q < L1; q++) rec[2 * q + h] = p[q];
    }
}

// ---------------- prefetch / stage (pure f4 memcpy, global layout == smem) ----------------
__device__ __forceinline__ void prefetch(int job, int t, float4* pf) {
    if (job >= NBLK) return;
    unsigned tt = g_tile[job];
    int ti = tt >> 8, tj = tt & 255;
    if (job < NBLK1) {
        const float4* As = (const float4*)(gP1 + ti * 16 * P1_REC);
        const float4* Bs = (const float4*)(gQ1 + tj * TS * Q1_STR);
#pragma unroll
        for (int k = 0; k < 4; k++) {
            int idx = t + k * PAIR_THREADS;
            if (idx < NA1_F4) pf[k] = As[idx];
            else if (idx < NA1_F4 + NB1_F4) pf[k] = Bs[idx - NA1_F4];
        }
    } else {
        const float4* As = (const float4*)(gP0 + ti * 16 * P0_REC);
        const float4* Bs = (const float4*)(gQ0 + tj * TS * Q0_STR);
#pragma unroll
        for (int k = 0; k < 2; k++) {
            int idx = t + k * PAIR_THREADS;
            if (idx < NA0_F4) pf[k] = As[idx];
            else if (idx < NA0_F4 + NB0_F4) pf[k] = Bs[idx - NA0_F4];
        }
    }
}

__device__ __forceinline__ void stage(bool d5, int t, const float4* pf,
                                      float4* sA4, float4* sB4) {
    if (d5) {
#pragma unroll
        for (int k = 0; k < 4; k++) {
            int idx = t + k * PAIR_THREADS;
            if (idx < NA1_F4) sA4[idx] = pf[k];
            else if (idx < NA1_F4 + NB1_F4) sB4[idx - NA1_F4] = pf[k];
        }
    } else {
#pragma unroll
        for (int k = 0; k < 2; k++) {
            int idx = t + k * PAIR_THREADS;
            if (idx < NA0_F4) sA4[idx] = pf[k];
            else if (idx < NA0_F4 + NB0_F4) sB4[idx - NA0_F4] = pf[k];
        }
    }
}

// ---------------- compute: generic dot-product tile ----------------
// warp w -> i's [4w, 4w+4) = packed pair-records 2w, 2w+1; lane -> j.
template <int L, int REC, int QSTR, int DVAL>
__device__ __forceinline__ void compute_tile(unsigned tt, const float* sA,
                                             const float* sB, int t, float& val) {
    const int ti = tt >> 8, tj = tt & 255;
    const int w = t >> 5, l = t & 31;
    const int j = tj * TS + l;
    const bool diag = (ti == tj);

    const ulonglong2* Ap0 = (const ulonglong2*)(sA + (2 * w) * REC);
    const ulonglong2* Ap1 = (const ulonglong2*)(sA + (2 * w + 1) * REC);
    const ulonglong2* Zp  = (const ulonglong2*)(sB + l * QSTR);

    ull accA0 = f2dup((float)DVAL), accB0 = 0ULL;  // pair0 chains (D folded)
    ull accA1 = f2dup((float)DVAL), accB1 = 0ULL;  // pair1 chains
#pragma unroll
    for (int qq = 0; qq < L / 2; qq++) {
        ulonglong2 z = Zp[qq];    // conflict-free LDS.128 (odd granule stride)
        ulonglong2 a0 = Ap0[qq];  // warp-uniform broadcast
        ulonglong2 a1 = Ap1[qq];
        accA0 = fma2(a0.x, z.x, accA0);
        accB0 = fma2(a0.y, z.y, accB0);
        accA1 = fma2(a1.x, z.x, accA1);
        accB1 = fma2(a1.y, z.y, accB1);
    }
    ull s0 = add2(accA0, accB0);
    ull s1 = add2(accA1, accB1);

    float lo, hi;
    const int ib = ti * TS + 4 * w;
    f2unpack(s0, lo, hi);
    lo = fmaxf(lo, 0.f);
    hi = fmaxf(hi, 0.f);
    if ((!diag || ib > j) && lo < 1.f) val += 1.f - sqrtf(lo);
    if ((!diag || ib + 1 > j) && hi < 1.f) val += 1.f - sqrtf(hi);
    f2unpack(s1, lo, hi);
    lo = fmaxf(lo, 0.f);
    hi = fmaxf(hi, 0.f);
    if ((!diag || ib + 2 > j) && lo < 1.f) val += 1.f - sqrtf(lo);
    if ((!diag || ib + 3 > j) && hi < 1.f) val += 1.f - sqrtf(hi);
}

// ---------------- Persistent, pipelined pair kernel ----------------
__global__ void __launch_bounds__(PAIR_THREADS, 4) pair_all_kernel(float* __restrict__ out) {
    __shared__ __align__(16) float sA[2][16 * P1_REC];   // 1280 fl / buf
    __shared__ __align__(16) float sB[2][TS * Q1_STR];   // 2688 fl / buf
    __shared__ float warp_sums[2][PAIR_THREADS / 32];

    const int t = threadIdx.x;
    float val0 = 0.f, val1 = 0.f;

    float4 pf[4];
    int job = blockIdx.x;
    prefetch(job, t, pf);
    int buf = 0;
    while (job < NBLK) {
        const bool d5 = (job < NBLK1);
        stage(d5, t, pf, (float4*)sA[buf], (float4*)sB[buf]);
        __syncthreads();  // single barrier per tile (double buffer)
        const unsigned tt = g_tile[job];
        prefetch(job + GRID_PAIR, t, pf);  // hidden under compute
        if (d5) compute_tile<L1, P1_REC, Q1_STR, D1>(tt, sA[buf], sB[buf], t, val1);
        else    compute_tile<L0, P0_REC, Q0_STR, D0>(tt, sA[buf], sB[buf], t, val0);
        buf ^= 1;
        job += GRID_PAIR;
    }

    // block reduction of both accumulators
#pragma unroll
    for (int off = 16; off > 0; off >>= 1) {
        val0 += __shfl_down_sync(0xFFFFFFFFu, val0, off);
        val1 += __shfl_down_sync(0xFFFFFFFFu, val1, off);
    }
    if ((t & 31) == 0) {
        warp_sums[0][t >> 5] = val0;
        warp_sums[1][t >> 5] = val1;
    }
    __syncthreads();
    if (t == 0) {
        float b0 = 0.f, b1 = 0.f;
#pragma unroll
        for (int ww = 0; ww < PAIR_THREADS / 32; ww++) {
            b0 += warp_sums[0][ww];
            b1 += warp_sums[1][ww];
        }
        if (b0 != 0.f) atomicAdd(&g_sum0, (double)b0);
        if (b1 != 0.f) atomicAdd(&g_sum1, (double)b1);
        __threadfence();
        unsigned int done = atomicAdd(&g_done, 1u);
        if (done == GRID_PAIR - 1) {
            __threadfence();
            double s0 = *(volatile double*)&g_sum0;
            double s1 = *(volatile double*)&g_sum1;
            double l0 = 2.0 * s0 / ((double)N0 * (double)(N0 - 1));
            double l1 = 2.0 * s1 / ((double)N1 * (double)(N1 - 1));
            out[0] = (float)(0.5 * (l0 + l1));
            g_done = 0;  // reset for next graph replay
        }
    }
}

extern "C" void kernel_launch(void* const* d_in, const int* in_sizes, int n_in,
                              void* d_out, int out_size) {
    const float* k0 = (const float*)d_in[0];
    const float* k1 = (const float*)d_in[1];
    float* out = (float*)d_out;

    prep_kernel<<<96, 32>>>(k0, k1);
    pair_all_kernel<<<GRID_PAIR, PAIR_THREADS>>>(out);
}

// round 11
// speedup vs baseline: 1.3072x; 1.0735x over previous
#include <cuda_runtime.h>
#include <math.h>

#define N0 2048
#define D0 3
#define N1 1024
#define D1 5
#define TS 32
#define PAIR_THREADS 256
#define GRID_PAIR 592               // 148 * 4

// dot-product lengths (padded to /4)
#define L0 16      // 9 + 6 + 1 pad
#define L1 40      // 25 + 15
#define P0_REC 32  // L0 * 2 halves (i-pair record)
#define P1_REC 80  // L1 * 2
#define Q0_STR 36  // L0*2 dup + 4 pad  (odd 16B-granule stride)
#define Q1_STR 84  // L1*2 dup + 4 pad  (odd)

// jobs: 528 D5 single tiles (heavy, first) + 1056 D3 double tiles
#define NJOB5 528
#define NJOB  1584
// smem buffer (floats): max(D5: 16*80+32*84=3968, D3x2: 16*32+2*32*36=2816)
#define SBUF 3968
// f4 region bounds
#define A5_F4 320   // 16*80/4
#define T5_F4 992   // + 32*84/4
#define A3_F4 128   // 16*32/4
#define B30_F4 416  // + 288
#define B31_F4 704  // + 288

typedef unsigned long long ull;

// Scratch (device globals: allocation-free per harness rules)
__device__ __align__(16) float gP0[(N0 / 2) * P0_REC];
__device__ __align__(16) float gQ0[N0 * Q0_STR];
__device__ __align__(16) float gP1[(N1 / 2) * P1_REC];
__device__ __align__(16) float gQ1[N1 * Q1_STR];
__device__ unsigned g_job[NJOB];
__device__ double g_sum0;
__device__ double g_sum1;
__device__ unsigned int g_done = 0;
__device__ int g_next;

// ---------------- packed f32x2 helpers (FFMA2: PTX-only) ----------------
__device__ __forceinline__ ull f2dup(float v) {
    ull r;
    asm("mov.b64 %0, {%1, %1};" : "=l"(r) : "f"(v));
    return r;
}
__device__ __forceinline__ void f2unpack(ull v, float& lo, float& hi) {
    asm("mov.b64 {%0, %1}, %2;" : "=f"(lo), "=f"(hi) : "l"(v));
}
__device__ __forceinline__ ull fma2(ull a, ull b, ull c) {
    ull d;
    asm("fma.rn.f32x2 %0, %1, %2, %3;" : "=l"(d) : "l"(a), "l"(b), "l"(c));
    return d;
}
__device__ __forceinline__ ull add2(ull a, ull b) {
    ull d;
    asm("add.rn.f32x2 %0, %1, %2;" : "=l"(d) : "l"(a), "l"(b));
    return d;
}
__device__ __forceinline__ unsigned smem_u32(const void* p) {
    unsigned a;
    asm("{ .reg .u64 t; cvta.to.shared.u64 t, %1; cvt.u32.u64 %0, t; }" : "=r"(a) : "l"(p));
    return a;
}
__device__ __forceinline__ void cpasync16(unsigned sdst, const void* gsrc) {
    asm volatile("cp.async.ca.shared.global [%0], [%1], 16;" :: "r"(sdst), "l"(gsrc) : "memory");
}

__device__ __forceinline__ void tri_decode(int b, int& ti, int& tj) {
    ti = (int)((sqrtf(8.f * (float)b + 1.f) - 1.f) * 0.5f);
    while ((ti + 1) * (ti + 2) / 2 <= b) ti++;
    while (ti * (ti + 1) / 2 > b) ti--;
    tj = b - ti * (ti + 1) / 2;
}

// ---------------- Fused prep: features + job table + dispatch counter ----------------
// s_ij = D + p_i . q_j   where p = [-2*inv ; sym(inv^T inv)], q = [kn^T ; sym(kn kn^T) dup-offdiag]
__global__ void __launch_bounds__(32) prep_kernel(const float* __restrict__ k0,
                                                  const float* __restrict__ k1) {
    int gid = blockIdx.x * 32 + threadIdx.x;
    if (gid == 0) {
        g_sum0 = 0.0;
        g_sum1 = 0.0;
        g_next = GRID_PAIR;
    }
    if (gid < NJOB) {
        if (gid < NJOB5) {  // D5 single-tile jobs, heavy first
            int ti, tj;
            tri_decode(gid, ti, tj);
            g_job[gid] = 0x80000000u | ((unsigned)ti << 8) | (unsigned)tj;
        } else {            // D3 2-tile jobs: row ti has ti/2+1 tj-pairs
            int jj = gid - NJOB5;
            int ti = 0, acc = 0;
            while (acc + (ti / 2 + 1) <= jj) { acc += ti / 2 + 1; ti++; }
            int tjp = jj - acc;
            g_job[gid] = ((unsigned)ti << 8) | (unsigned)tjp;
        }
    }

    if (blockIdx.x < 64) {
        int i = gid;  // layer0 matrix
        float a[9];
        float ss = 0.f;
#pragma unroll
        for (int t = 0; t < 9; t++) {
            a[t] = k0[i * 9 + t];
            ss = fmaf(a[t], a[t], ss);
        }
        float rn = 1.f / (sqrtf(ss) + 1e-8f);
#pragma unroll
        for (int t = 0; t < 9; t++) a[t] *= rn;

        float z[L0];
#pragma unroll
        for (int r = 0; r < 3; r++)
#pragma unroll
            for (int k = 0; k < 3; k++)
                z[r * 3 + k] = a[k * 3 + r];
#pragma unroll
        for (int x = 0; x < 3; x++) {
            float h = 0.f;
#pragma unroll
            for (int c = 0; c < 3; c++) h = fmaf(a[x * 3 + c], a[x * 3 + c], h);
            z[9 + x] = h;
        }
        {
            int m = 0;
#pragma unroll
            for (int x = 0; x < 3; x++)
#pragma unroll
                for (int y = x + 1; y < 3; y++) {
                    float h = 0.f;
#pragma unroll
                    for (int c = 0; c < 3; c++) h = fmaf(a[x * 3 + c], a[y * 3 + c], h);
                    z[12 + m] = 2.f * h;
                    m++;
                }
        }
        z[15] = 0.f;
        float* qrow = &gQ0[i * Q0_STR];
#pragma unroll
        for (int q = 0; q < L0; q++) {
            qrow[2 * q + 0] = z[q];
            qrow[2 * q + 1] = z[q];
        }
#pragma unroll
        for (int q = 2 * L0; q < Q0_STR; q++) qrow[q] = 0.f;

        float inv[9];
        float c00 = a[4] * a[8] - a[5] * a[7];
        float c10 = a[5] * a[6] - a[3] * a[8];
        float c20 = a[3] * a[7] - a[4] * a[6];
        float det = a[0] * c00 + a[1] * c10 + a[2] * c20;
        float id = 1.f / det;
        inv[0] = c00 * id;
        inv[1] = (a[2] * a[7] - a[1] * a[8]) * id;
        inv[2] = (a[1] * a[5] - a[2] * a[4]) * id;
        inv[3] = c10 * id;
        inv[4] = (a[0] * a[8] - a[2] * a[6]) * id;
        inv[5] = (a[2] * a[3] - a[0] * a[5]) * id;
        inv[6] = c20 * id;
        inv[7] = (a[1] * a[6] - a[0] * a[7]) * id;
        inv[8] = (a[0] * a[4] - a[1] * a[3]) * id;

        float p[L0];
#pragma unroll
        for (int t = 0; t < 9; t++) p[t] = -2.f * inv[t];
#pragma unroll
        for (int x = 0; x < 3; x++) {
            float g = 0.f;
#pragma unroll
            for (int r = 0; r < 3; r++) g = fmaf(inv[r * 3 + x], inv[r * 3 + x], g);
            p[9 + x] = g;
        }
        {
            int m = 0;
#pragma unroll
            for (int x = 0; x < 3; x++)
#pragma unroll
                for (int y = x + 1; y < 3; y++) {
                    float g = 0.f;
#pragma unroll
                    for (int r = 0; r < 3; r++) g = fmaf(inv[r * 3 + x], inv[r * 3 + y], g);
                    p[12 + m] = g;
                    m++;
                }
        }
        p[15] = 0.f;
        int pair = i >> 1, h = i & 1;
        float* rec = &gP0[pair * P0_REC];
#pragma unroll
        for (int q = 0; q < L0; q++) rec[2 * q + h] = p[q];
    } else {
        int i = gid - 2048;  // layer1 matrix
        float a[5][5], b[5][5];
        float ss = 0.f;
#pragma unroll
        for (int r = 0; r < 5; r++)
#pragma unroll
            for (int c = 0; c < 5; c++) {
                float v = k1[i * 25 + r * 5 + c];
                a[r][c] = v;
                ss = fmaf(v, v, ss);
            }
        float rn = 1.f / (sqrtf(ss) + 1e-8f);
#pragma unroll
        for (int r = 0; r < 5; r++)
#pragma unroll
            for (int c = 0; c < 5; c++) {
                a[r][c] *= rn;
                b[r][c] = (r == c) ? 1.f : 0.f;
            }

        float z[L1];
#pragma unroll
        for (int r = 0; r < 5; r++)
#pragma unroll
            for (int k = 0; k < 5; k++)
                z[r * 5 + k] = a[k][r];
#pragma unroll
        for (int x = 0; x < 5; x++) {
            float h = 0.f;
#pragma unroll
            for (int c = 0; c < 5; c++) h = fmaf(a[x][c], a[x][c], h);
            z[25 + x] = h;
        }
        {
            int m = 0;
#pragma unroll
            for (int x = 0; x < 5; x++)
#pragma unroll
                for (int y = x + 1; y < 5; y++) {
                    float h = 0.f;
#pragma unroll
                    for (int c = 0; c < 5; c++) h = fmaf(a[x][c], a[y][c], h);
                    z[30 + m] = 2.f * h;
                    m++;
                }
        }
        float* qrow = &gQ1[i * Q1_STR];
#pragma unroll
        for (int q = 0; q < L1; q++) {
            qrow[2 * q + 0] = z[q];
            qrow[2 * q + 1] = z[q];
        }
#pragma unroll
        for (int q = 2 * L1; q < Q1_STR; q++) qrow[q] = 0.f;

#pragma unroll
        for (int col = 0; col < 5; col++) {
#pragma unroll
            for (int r = col + 1; r < 5; r++) {
                bool sw = fabsf(a[r][col]) > fabsf(a[col][col]);
#pragma unroll
                for (int c = 0; c < 5; c++) {
                    float t0 = a[col][c], t1 = a[r][c];
                    a[col][c] = sw ? t1 : t0;
                    a[r][c]   = sw ? t0 : t1;
                    float u0 = b[col][c], u1 = b[r][c];
                    b[col][c] = sw ? u1 : u0;
                    b[r][c]   = sw ? u0 : u1;
                }
            }
            float piv = 1.f / a[col][col];
#pragma unroll
            for (int c = 0; c < 5; c++) {
                a[col][c] *= piv;
                b[col][c] *= piv;
            }
#pragma unroll
            for (int r = 0; r < 5; r++) {
                if (r == col) continue;
                float f = a[r][col];
#pragma unroll
                for (int c = 0; c < 5; c++) {
                    a[r][c] = fmaf(-f, a[col][c], a[r][c]);
                    b[r][c] = fmaf(-f, b[col][c], b[r][c]);
                }
            }
        }

        float p[L1];
#pragma unroll
        for (int r = 0; r < 5; r++)
#pragma unroll
            for (int k = 0; k < 5; k++)
                p[r * 5 + k] = -2.f * b[r][k];
#pragma unroll
        for (int x = 0; x < 5; x++) {
            float g = 0.f;
#pragma unroll
            for (int r = 0; r < 5; r++) g = fmaf(b[r][x], b[r][x], g);
            p[25 + x] = g;
        }
        {
            int m = 0;
#pragma unroll
            for (int x = 0; x < 5; x++)
#pragma unroll
                for (int y = x + 1; y < 5; y++) {
                    float g = 0.f;
#pragma unroll
                    for (int r = 0; r < 5; r++) g = fmaf(b[r][x], b[r][y], g);
                    p[30 + m] = g;
                    m++;
                }
        }
        int pair = i >> 1, h = i & 1;
        float* rec = &gP1[pair * P1_REC];
#pragma unroll
        for (int q = 0; q < L1; q++) rec[2 * q + h] = p[q];
    }
}

// ---------------- cp.async staging of one job into a smem buffer ----------------
__device__ __forceinline__ void issue_copies(int job, float* sdst, int t) {
    unsigned jd = g_job[job];
    unsigned sa = smem_u32(sdst);
    int ti = (jd >> 8) & 255;
    if (jd & 0x80000000u) {  // D5 single tile
        int tj = jd & 255;
        const float4* A = ((const float4*)gP1) + ti * (16 * P1_REC / 4);
        const float4* B = ((const float4*)gQ1) + tj * (TS * Q1_STR / 4);
#pragma unroll
        for (int k = 0; k < 4; k++) {
            int idx = t + k * PAIR_THREADS;
            if (idx < A5_F4) cpasync16(sa + idx * 16, A + idx);
            else if (idx < T5_F4) cpasync16(sa + idx * 16, B + (idx - A5_F4));
        }
    } else {                 // D3 double tile (tj0 = 2*tjp, tj0+1 row-contiguous in gQ0)
        int tjp = jd & 255;
        int tj0 = 2 * tjp;
        bool two = (tj0 + 1 <= ti);
        const float4* A = ((const float4*)gP0) + ti * (16 * P0_REC / 4);
        const float4* B0 = ((const float4*)gQ0) + tj0 * (TS * Q0_STR / 4);
#pragma unroll
        for (int k = 0; k < 3; k++) {
            int idx = t + k * PAIR_THREADS;
            if (idx < A3_F4) cpasync16(sa + idx * 16, A + idx);
            else if (idx < B30_F4) cpasync16(sa + idx * 16, B0 + (idx - A3_F4));
            else if (idx < B31_F4 && two) cpasync16(sa + idx * 16, B0 + (idx - A3_F4));
        }
    }
}

// ---------------- epilogue for one packed s-pair ----------------
__device__ __forceinline__ void finish(ull s, int ibase, int j, bool diag, float& val) {
    float lo, hi;
    f2unpack(s, lo, hi);
    lo = fmaxf(lo, 0.f);
    hi = fmaxf(hi, 0.f);
    if ((!diag || ibase > j) && lo < 1.f) val += 1.f - sqrtf(lo);
    if ((!diag || ibase + 1 > j) && hi < 1.f) val += 1.f - sqrtf(hi);
}

// ---------------- compute: D5 single tile ----------------
__device__ __forceinline__ void compute5(unsigned jd, const float* s, int t, float& val) {
    const int ti = (jd >> 8) & 255, tj = jd & 255;
    const int w = t >> 5, l = t & 31;
    const int j = tj * TS + l;
    const bool diag = (ti == tj);
    const ulonglong2* Ap0 = (const ulonglong2*)(s + (2 * w) * P1_REC);
    const ulonglong2* Ap1 = (const ulonglong2*)(s + (2 * w + 1) * P1_REC);
    const ulonglong2* Zp  = (const ulonglong2*)(s + 4 * A5_F4 + l * Q1_STR);

    ull xa = f2dup((float)D1), xb = 0ULL, ya = f2dup((float)D1), yb = 0ULL;
#pragma unroll
    for (int qq = 0; qq < L1 / 2; qq++) {
        ulonglong2 z = Zp[qq];
        ulonglong2 a0 = Ap0[qq];
        ulonglong2 a1 = Ap1[qq];
        xa = fma2(a0.x, z.x, xa);
        xb = fma2(a0.y, z.y, xb);
        ya = fma2(a1.x, z.x, ya);
        yb = fma2(a1.y, z.y, yb);
    }
    const int ib = ti * TS + 4 * w;
    finish(add2(xa, xb), ib, j, diag, val);
    finish(add2(ya, yb), ib + 2, j, diag, val);
}

// ---------------- compute: D3 double tile (A loads shared in registers) ----------------
__device__ __forceinline__ void compute3x2(unsigned jd, const float* s, int t, float& val) {
    const int ti = (jd >> 8) & 255, tjp = jd & 255;
    const int tj0 = 2 * tjp;
    const bool two = (tj0 + 1 <= ti);
    const int w = t >> 5, l = t & 31;
    const ulonglong2* Ap0 = (const ulonglong2*)(s + (2 * w) * P0_REC);
    const ulonglong2* Ap1 = (const ulonglong2*)(s + (2 * w + 1) * P0_REC);
    const ulonglong2* Z0  = (const ulonglong2*)(s + 4 * A3_F4 + l * Q0_STR);
    const ulonglong2* Z1  = (const ulonglong2*)(s + 4 * A3_F4 + TS * Q0_STR + l * Q0_STR);

    ull x0a = f2dup((float)D0), x0b = 0ULL, y0a = f2dup((float)D0), y0b = 0ULL;
    ull x1a = x0a, x1b = 0ULL, y1a = x0a, y1b = 0ULL;
    if (two) {
#pragma unroll
        for (int qq = 0; qq < L0 / 2; qq++) {
            ulonglong2 a0 = Ap0[qq];
            ulonglong2 a1 = Ap1[qq];
            ulonglong2 z0 = Z0[qq];
            ulonglong2 z1 = Z1[qq];
            x0a = fma2(a0.x, z0.x, x0a);
            x0b = fma2(a0.y, z0.y, x0b);
            y0a = fma2(a1.x, z0.x, y0a);
            y0b = fma2(a1.y, z0.y, y0b);
            x1a = fma2(a0.x, z1.x, x1a);
            x1b = fma2(a0.y, z1.y, x1b);
            y1a = fma2(a1.x, z1.x, y1a);
            y1b = fma2(a1.y, z1.y, y1b);
        }
    } else {
#pragma unroll
        for (int qq = 0; qq < L0 / 2; qq++) {
            ulonglong2 a0 = Ap0[qq];
            ulonglong2 a1 = Ap1[qq];
            ulonglong2 z0 = Z0[qq];
            x0a = fma2(a0.x, z0.x, x0a);
            x0b = fma2(a0.y, z0.y, x0b);
            y0a = fma2(a1.x, z0.x, y0a);
            y0b = fma2(a1.y, z0.y, y0b);
        }
    }
    const int ib = ti * TS + 4 * w;
    {
        const int j = tj0 * TS + l;
        const bool diag = (ti == tj0);
        finish(add2(x0a, x0b), ib, j, diag, val);
        finish(add2(y0a, y0b), ib + 2, j, diag, val);
    }
    if (two) {
        const int j = (tj0 + 1) * TS + l;
        const bool diag = (ti == tj0 + 1);
        finish(add2(x1a, x1b), ib, j, diag, val);
        finish(add2(y1a, y1b), ib + 2, j, diag, val);
    }
}

// ---------------- Persistent pair kernel: cp.async pipeline + dynamic LPT dispatch ----------------
__global__ void __launch_bounds__(PAIR_THREADS, 4) pair_all_kernel(float* __restrict__ out) {
    __shared__ __align__(16) float sbuf[2][SBUF];
    __shared__ float warp_sums[2][PAIR_THREADS / 32];
    __shared__ int s_next;

    const int t = threadIdx.x;
    float val0 = 0.f, val1 = 0.f;

    int curr = blockIdx.x;  // GRID_PAIR < NJOB: always valid
    issue_copies(curr, sbuf[0], t);
    asm volatile("cp.async.commit_group;" ::: "memory");
    if (t == 0) s_next = atomicAdd(&g_next, 1);
    asm volatile("cp.async.wait_group 0;" ::: "memory");
    __syncthreads();
    int nxt = s_next;
    int buf = 0;

    while (true) {
        if (nxt < NJOB) {
            issue_copies(nxt, sbuf[buf ^ 1], t);
            if (t == 0) s_next = atomicAdd(&g_next, 1);
        }
        asm volatile("cp.async.commit_group;" ::: "memory");
        unsigned jd = g_job[curr];
        if (jd & 0x80000000u) compute5(jd, sbuf[buf], t, val1);
        else                  compute3x2(jd, sbuf[buf], t, val0);
        if (nxt >= NJOB) break;
        asm volatile("cp.async.wait_group 0;" ::: "memory");
        __syncthreads();
        curr = nxt;
        nxt = s_next;
        buf ^= 1;
    }

    // block reduction of both accumulators
#pragma unroll
    for (int off = 16; off > 0; off >>= 1) {
        val0 += __shfl_down_sync(0xFFFFFFFFu, val0, off);
        val1 += __shfl_down_sync(0xFFFFFFFFu, val1, off);
    }
    if ((t & 31) == 0) {
        warp_sums[0][t >> 5] = val0;
        warp_sums[1][t >> 5] = val1;
    }
    __syncthreads();
    if (t == 0) {
        float b0 = 0.f, b1 = 0.f;
#pragma unroll
        for (int ww = 0; ww < PAIR_THREADS / 32; ww++) {
            b0 += warp_sums[0][ww];
            b1 += warp_sums[1][ww];
        }
        if (b0 != 0.f) atomicAdd(&g_sum0, (double)b0);
        if (b1 != 0.f) atomicAdd(&g_sum1, (double)b1);
        __threadfence();
        unsigned int done = atomicAdd(&g_done, 1u);
        if (done == GRID_PAIR - 1) {
            __threadfence();
            double s0 = *(volatile double*)&g_sum0;
            double s1 = *(volatile double*)&g_sum1;
            double l0 = 2.0 * s0 / ((double)N0 * (double)(N0 - 1));
            double l1 = 2.0 * s1 / ((double)N1 * (double)(N1 - 1));
            out[0] = (float)(0.5 * (l0 + l1));
            g_done = 0;  // reset for next graph replay
        }
    }
}

extern "C" void kernel_launch(void* const* d_in, const int* in_sizes, int n_in,
                              void* d_out, int out_size) {
    const float* k0 = (const float*)d_in[0];
    const float* k1 = (const float*)d_in[1];
    float* out = (float*)d_out;

    prep_kernel<<<96, 32>>>(k0, k1);
    pair_all_kernel<<<GRID_PAIR, PAIR_THREADS>>>(out);
}